// round 3
// baseline (speedup 1.0000x reference)
#include <cuda_runtime.h>
#include <cstdint>
#include <cstddef>

// ---------------- problem constants ----------------
#define BATCH 16384
#define JNT   17
#define FIN   256
#define FOUT  256
#define MROWS (BATCH * JNT)          // 278528 = 2176 * 128
#define KTOT  (3 * FIN)              // 768

// GEMM tiling
#define BM 128
#define BN 256
#define BK 32
#define NKIT (KTOT / BK)             // 24 k-iterations
#define NSTAGE 3
#define ASTRIDE 40                   // words per A smem row (pad for conflict-free LDS.64)
#define BSTRIDE 40                   // words per B smem row
#define ASZW (BM * ASTRIDE)          // 5120 words
#define BSZW (BN * BSTRIDE)          // 10240 words
#define STGW (ASZW + BSZW)           // 15360 words per stage
#define SMEM_BYTES (NSTAGE * STGW * 4)   // 184320 bytes

// ---------------- device scratch (static, no runtime allocation) ----------------
__device__ float g_z[(size_t)MROWS * KTOT];            // zcat, k-interleaved, tf32-rounded (~856MB)
__device__ float g_wb[(size_t)NKIT * BN * BSTRIDE];    // Wcat prepacked as per-k-iter smem images (~1MB)

// ---------------- helpers ----------------
__device__ __forceinline__ uint32_t smem_u32(const void* p) {
    uint32_t a;
    asm("{ .reg .u64 t; cvta.to.shared.u64 t, %1; cvt.u32.u64 %0, t; }" : "=r"(a) : "l"(p));
    return a;
}

__device__ __forceinline__ float rtf32(float v) {
    uint32_t r;
    asm("cvt.rn.tf32.f32 %0, %1;" : "=r"(r) : "f"(v));
    return __uint_as_float(r);
}

__device__ __forceinline__ void cp16(uint32_t dst, const void* src) {
    asm volatile("cp.async.cg.shared.global [%0], [%1], 16;" :: "r"(dst), "l"(src));
}
#define CP_COMMIT() asm volatile("cp.async.commit_group;" ::: "memory")
#define CP_WAIT1()  asm volatile("cp.async.wait_group 1;" ::: "memory")

// mma.sync m16n8k8 tf32: d += a*b (fp32 accumulate). Arch-neutral PTX (sm_80+).
__device__ __forceinline__ void mma_tf32(float* d, uint32_t a0, uint32_t a1,
                                         uint32_t a2, uint32_t a3,
                                         uint32_t b0, uint32_t b1) {
    asm volatile(
        "mma.sync.aligned.m16n8k8.row.col.f32.tf32.tf32.f32 "
        "{%0,%1,%2,%3}, {%4,%5,%6,%7}, {%8,%9}, {%0,%1,%2,%3};"
        : "+f"(d[0]), "+f"(d[1]), "+f"(d[2]), "+f"(d[3])
        : "r"(a0), "r"(a1), "r"(a2), "r"(a3), "r"(b0), "r"(b1));
}

// k-interleave permutation within each 8-group: element k goes to position
// p = (k&3)*2 + (k>>2), so that (k, k+4) pairs sit adjacently for LDS.64.
// pcol(f): position of original column f within a row of interleaved 8-groups.
__device__ __forceinline__ int pcol_of(int f) {
    return ((f >> 3) << 3) + ((f & 3) << 1) + ((f >> 2) & 1);
}

// ---------------- kernel 0: prepack Wcat into per-k-iter smem images ----------------
// g_wb[t][n][p] with p in [0,40): p<32 holds W[k = t*32 + (p>>3)*8 + invperm(p&7)][n]
// (tf32-rounded), p>=32 is padding (zero).
__global__ void __launch_bounds__(256) wprep_kernel(const float* __restrict__ W) {
    int idx = blockIdx.x * 256 + threadIdx.x;         // NKIT*BN*BSTRIDE = 245760 total
    int p = idx % BSTRIDE;
    int n = (idx / BSTRIDE) % BN;
    int t = idx / (BSTRIDE * BN);
    float v = 0.0f;
    if (p < 32) {
        int s = p >> 3, q = p & 7;
        int w = (q >> 1) + ((q & 1) << 2);            // inverse of perm
        int k = t * 32 + s * 8 + w;
        v = rtf32(W[k * FOUT + n]);                   // Wcat row k = (part,f), col n = o
    }
    g_wb[idx] = v;
}

// ---------------- kernel 1: aggregate-first  z[b,i,(part,f)] ----------------
// z0 = adj[i,i]*x[b,i,f]; z1 = sum_{j>i} adj[i,j]*x[b,j,f]; z2 = sum_{j<i} ...
// Written tf32-rounded, with within-8-group k-interleave matching the GEMM A layout.
__global__ void __launch_bounds__(256) agg_kernel(const float* __restrict__ x,
                                                  const float* __restrict__ adj) {
    __shared__ float sx[JNT * FIN];
    __shared__ float sadj[JNT * JNT];
    const int b = blockIdx.x;
    const int tid = threadIdx.x;

    const float4* xs = (const float4*)(x + (size_t)b * JNT * FIN);
    float4* sd = (float4*)sx;
    for (int t = tid; t < JNT * FIN / 4; t += 256) sd[t] = xs[t];
    for (int t = tid; t < JNT * JNT; t += 256) sadj[t] = adj[t];
    __syncthreads();

    float xv[JNT];
    #pragma unroll
    for (int j = 0; j < JNT; j++) xv[j] = sx[j * FIN + tid];

    const int pc = pcol_of(tid);
    float* zr = g_z + (size_t)b * JNT * KTOT;

    #pragma unroll
    for (int i = 0; i < JNT; i++) {
        float s1 = 0.0f, s2 = 0.0f;
        #pragma unroll
        for (int j = 0; j < JNT; j++) {
            float a = sadj[i * JNT + j];
            if (j > i) s1 += a * xv[j];
            if (j < i) s2 += a * xv[j];
        }
        float d = sadj[i * JNT + i] * xv[i];
        float* zi = zr + i * KTOT;
        zi[pc]             = rtf32(d);
        zi[FIN + pc]       = rtf32(s1);
        zi[2 * FIN + pc]   = rtf32(s2);
    }
}

// ---------------- kernel 2: GEMM  out = z @ Wcat + bias ----------------
// CTA 128x256, 8 warps of 64x64 (warp_m in {0,1}, warp_n in {0..3}),
// mma.sync m16n8k8 tf32, 3-stage cp.async pipeline.
struct SmemView { float* A; float* B; };

__device__ __forceinline__ void load_stage(uint32_t sb, int t, int s, int tid, size_t mbase) {
    // A tile: z rows [mbase..mbase+127], k slice [t*32, t*32+32)
    const float* za = g_z + mbase * KTOT + t * BK;
    uint32_t as = sb + (uint32_t)s * STGW * 4;
    #pragma unroll
    for (int q = 0; q < 4; q++) {
        int id = tid + q * 256;                        // 1024 16B chunks
        int row = id >> 3, ck = id & 7;
        cp16(as + row * (ASTRIDE * 4) + ck * 16, za + (size_t)row * KTOT + ck * 4);
    }
    // B tile: prepacked, straight copy of 40960 bytes
    const float* wb = g_wb + (size_t)t * BSZW;
    uint32_t bs = sb + (uint32_t)s * STGW * 4 + ASZW * 4;
    #pragma unroll
    for (int q = 0; q < 10; q++) {
        int id = tid + q * 256;                        // 2560 16B chunks
        cp16(bs + id * 16, wb + id * 4);
    }
}

__global__ void __launch_bounds__(256, 1) gemm_kernel(float* __restrict__ out,
                                                      const float* __restrict__ bias) {
    extern __shared__ float sm[];
    const uint32_t sb = smem_u32(sm);
    const int tid = threadIdx.x;
    const int wid = tid >> 5;
    const int lane = tid & 31;
    const int warp_m = wid & 1;      // 2 x 64 = 128 M
    const int warp_n = wid >> 1;     // 4 x 64 = 256 N
    const int r = lane >> 2;         // 0..7
    const int c = lane & 3;          // 0..3
    const size_t mbase = (size_t)blockIdx.x * BM;

    float acc[128];
    #pragma unroll
    for (int i = 0; i < 128; i++) acc[i] = 0.0f;

    // prologue: prefetch stages 0,1
    load_stage(sb, 0, 0, tid, mbase); CP_COMMIT();
    load_stage(sb, 1, 1, tid, mbase); CP_COMMIT();

    for (int t = 0; t < NKIT; t++) {
        CP_WAIT1();
        __syncthreads();
        if (t + NSTAGE - 1 < NKIT)
            load_stage(sb, t + NSTAGE - 1, (t + NSTAGE - 1) % NSTAGE, tid, mbase);
        CP_COMMIT();

        const float* As = sm + (t % NSTAGE) * STGW;
        const float* Bs = As + ASZW;

        #pragma unroll
        for (int s = 0; s < 4; s++) {                  // 4 k-steps of 8
            uint2 aF[4][2];
            #pragma unroll
            for (int mt = 0; mt < 4; mt++) {
                const float* ap = As + (warp_m * 64 + mt * 16 + r) * ASTRIDE + s * 8 + 2 * c;
                aF[mt][0] = *(const uint2*)ap;                      // (a0, a2): k=c, c+4
                aF[mt][1] = *(const uint2*)(ap + 8 * ASTRIDE);      // (a1, a3): row+8
            }
            uint2 bF[8];
            #pragma unroll
            for (int nt = 0; nt < 8; nt++) {
                const float* bp = Bs + (warp_n * 64 + nt * 8 + r) * BSTRIDE + s * 8 + 2 * c;
                bF[nt] = *(const uint2*)bp;                          // (b0, b1): k=c, c+4
            }
            #pragma unroll
            for (int mt = 0; mt < 4; mt++)
                #pragma unroll
                for (int nt = 0; nt < 8; nt++)
                    mma_tf32(&acc[(mt * 8 + nt) * 4],
                             aF[mt][0].x, aF[mt][1].x, aF[mt][0].y, aF[mt][1].y,
                             bF[nt].x, bF[nt].y);
        }
        __syncthreads();
    }

    // epilogue: + bias, write fp32 out
    #pragma unroll
    for (int mt = 0; mt < 4; mt++) {
        size_t gm = mbase + warp_m * 64 + mt * 16 + r;
        float* o0 = out + gm * FOUT;
        #pragma unroll
        for (int nt = 0; nt < 8; nt++) {
            int col = warp_n * 64 + nt * 8 + 2 * c;
            float b0 = __ldg(bias + col), b1 = __ldg(bias + col + 1);
            const float* a = &acc[(mt * 8 + nt) * 4];
            *(float2*)(o0 + col)             = make_float2(a[0] + b0, a[1] + b1);
            *(float2*)(o0 + 8 * FOUT + col)  = make_float2(a[2] + b0, a[3] + b1);
        }
    }
}

// ---------------- launch ----------------
extern "C" void kernel_launch(void* const* d_in, const int* in_sizes, int n_in,
                              void* d_out, int out_size) {
    const float* x    = (const float*)d_in[0];   // [16384,17,256]
    const float* W    = (const float*)d_in[1];   // [3,256,256] == Wcat [768,256]
    const float* adj  = (const float*)d_in[2];   // [17,17]
    const float* bias = (const float*)d_in[3];   // [256]
    float* out = (float*)d_out;                  // [16384,17,256]

    cudaFuncSetAttribute(gemm_kernel, cudaFuncAttributeMaxDynamicSharedMemorySize, SMEM_BYTES);

    wprep_kernel<<<(NKIT * BN * BSTRIDE) / 256, 256>>>(W);
    agg_kernel<<<BATCH, 256>>>(x, adj);
    gemm_kernel<<<MROWS / BM, 256, SMEM_BYTES>>>(out, bias);
}